// round 1
// baseline (speedup 1.0000x reference)
#include <cuda_runtime.h>
#include <cstdint>
#include <cstddef>

// ---------------- static device scratch (no allocations allowed) ----------------
#define MAXN 100352
#define MAXE 1601536
#define MAXNB 128

__device__ int   g_src[MAXE];
__device__ int   g_dst[MAXE];
__device__ int   g_srcs[MAXE];     // src sorted by dst (CSR order)
__device__ float g_ws[MAXE];       // edge weight in CSR order
__device__ int   g_deg[MAXN];
__device__ int   g_fill[MAXN];
__device__ int   g_rowptr[MAXN + 1];
__device__ float g_sumw[MAXN];
__device__ float g_meanw[MAXN];
__device__ float g_xl[(size_t)MAXN * 128];
__device__ float g_h[(size_t)MAXN * 128];
__device__ float g_asrc[MAXN];
__device__ float g_adst[MAXN];
__device__ float g_c[1];
__device__ int   g_is64[1];
__device__ int   g_bsums[MAXNB];
__device__ int   g_boffs[MAXNB];

// ---------------- dtype detection: int64 edge_index has all-zero odd words ----------------
__global__ void k_detect(const unsigned int* p, long long nwords) {
    __shared__ int s_any;
    if (threadIdx.x == 0) s_any = 0;
    __syncthreads();
    int any = 0;
    for (int j = 0; j < 32; j++) {
        long long idx = 1 + 2LL * (threadIdx.x * 32 + j);
        if (idx < nwords && p[idx] != 0u) any = 1;
    }
    if (any) atomicOr(&s_any, 1);
    __syncthreads();
    if (threadIdx.x == 0) g_is64[0] = (s_any == 0) ? 1 : 0;
}

__global__ void k_extract(const void* ei, int E) {
    int i = blockIdx.x * blockDim.x + threadIdx.x;
    if (i >= E) return;
    if (g_is64[0]) {
        const long long* p = (const long long*)ei;
        g_src[i] = (int)p[i];
        g_dst[i] = (int)p[(size_t)E + i];
    } else {
        const int* p = (const int*)ei;
        g_src[i] = p[i];
        g_dst[i] = p[E + i];
    }
}

// ---------------- CSR build ----------------
__global__ void k_zero(int n) {
    int i = blockIdx.x * blockDim.x + threadIdx.x;
    if (i < n) { g_deg[i] = 0; g_fill[i] = 0; g_sumw[i] = 0.f; }
}

__global__ void k_count(const float* __restrict__ w, int E) {
    int i = blockIdx.x * blockDim.x + threadIdx.x;
    if (i >= E) return;
    int d = g_dst[i];
    atomicAdd(&g_deg[d], 1);
    atomicAdd(&g_sumw[d], w[i]);
}

__global__ void k_scanA(int n) {
    __shared__ int s[1024];
    int b = blockIdx.x, t = threadIdx.x;
    int i = b * 1024 + t;
    int v = (i < n) ? g_deg[i] : 0;
    s[t] = v;
    __syncthreads();
    for (int off = 1; off < 1024; off <<= 1) {
        int x = (t >= off) ? s[t - off] : 0;
        __syncthreads();
        s[t] += x;
        __syncthreads();
    }
    if (i < n) g_rowptr[i] = s[t] - v;   // exclusive within block
    if (t == 1023) g_bsums[b] = s[1023];
}

__global__ void k_scanB(int nb, int n) {
    if (threadIdx.x == 0) {
        int run = 0;
        for (int b = 0; b < nb; b++) { g_boffs[b] = run; run += g_bsums[b]; }
        g_rowptr[n] = run;
    }
}

__global__ void k_scanC(int n) {
    int i = blockIdx.x * 1024 + threadIdx.x;
    if (i < n) g_rowptr[i] += g_boffs[blockIdx.x];
}

__global__ void k_fill(const float* __restrict__ w, int E) {
    int i = blockIdx.x * blockDim.x + threadIdx.x;
    if (i >= E) return;
    int d = g_dst[i];
    int pos = g_rowptr[d] + atomicAdd(&g_fill[d], 1);
    g_srcs[pos] = g_src[i];
    g_ws[pos] = w[i];
}

__global__ void k_meanw(int n) {
    int i = blockIdx.x * blockDim.x + threadIdx.x;
    if (i < n) {
        int d = g_deg[i];
        g_meanw[i] = (d > 0) ? g_sumw[i] / (float)d : 0.f;
    }
}

// ---------------- GEMM: C[n,KOUT] = A[n,128] @ W[128,KOUT] ----------------
template <int KOUT>
__global__ __launch_bounds__(256) void k_gemm(const float* __restrict__ A,
                                              const float* __restrict__ W,
                                              float* __restrict__ C, int n) {
    constexpr int KIN = 128, BM = 128, KT = 32, TN = KOUT / 16;
    __shared__ float Xs[KT][BM + 1];                 // transposed tile, stride 129 (conflict-free)
    __shared__ __align__(16) float Wsm[KT][KOUT];
    int t = threadIdx.x;
    int tx = t & 15, ty = t >> 4;
    int row0 = blockIdx.x * BM;

    float acc[8][TN];
#pragma unroll
    for (int i = 0; i < 8; i++)
#pragma unroll
        for (int j = 0; j < TN; j++) acc[i][j] = 0.f;

    for (int k0 = 0; k0 < KIN; k0 += KT) {
        // load X tile transposed: Xs[k][r]
#pragma unroll
        for (int it = 0; it < 4; ++it) {
            int r = (t >> 3) + it * 32;
            int k4 = (t & 7) * 4;
            float4 v = make_float4(0.f, 0.f, 0.f, 0.f);
            int gr = row0 + r;
            if (gr < n) v = *(const float4*)&A[(size_t)gr * KIN + k0 + k4];
            Xs[k4 + 0][r] = v.x;
            Xs[k4 + 1][r] = v.y;
            Xs[k4 + 2][r] = v.z;
            Xs[k4 + 3][r] = v.w;
        }
        // load W tile
        constexpr int WT = KT * KOUT / 4 / 256;
#pragma unroll
        for (int it = 0; it < WT; ++it) {
            int idx = t + it * 256;
            int kk = idx / (KOUT / 4);
            int c4 = (idx % (KOUT / 4)) * 4;
            *(float4*)&Wsm[kk][c4] = *(const float4*)&W[(size_t)(k0 + kk) * KOUT + c4];
        }
        __syncthreads();
#pragma unroll
        for (int k = 0; k < KT; k++) {
            float a[8], bb[TN];
#pragma unroll
            for (int i = 0; i < 8; i++) a[i] = Xs[k][ty * 8 + i];
#pragma unroll
            for (int j = 0; j < TN; j++) bb[j] = Wsm[k][tx + 16 * j];
#pragma unroll
            for (int i = 0; i < 8; i++)
#pragma unroll
                for (int j = 0; j < TN; j++) acc[i][j] = fmaf(a[i], bb[j], acc[i][j]);
        }
        __syncthreads();
    }
#pragma unroll
    for (int i = 0; i < 8; i++) {
        int r = row0 + ty * 8 + i;
        if (r < n) {
#pragma unroll
            for (int j = 0; j < TN; j++) C[(size_t)r * KOUT + tx + 16 * j] = acc[i][j];
        }
    }
}

// ---------------- per-node attention logits: asrc = xl.a_s, adst = xl.a_d ----------------
template <int D>
__global__ void k_dots(const float* __restrict__ xl, const float* __restrict__ a_s,
                       const float* __restrict__ a_d, int n) {
    int w = (blockIdx.x * blockDim.x + threadIdx.x) >> 5;
    int lane = threadIdx.x & 31;
    if (w >= n) return;
    float s1 = 0.f, s2 = 0.f;
#pragma unroll
    for (int k = lane; k < D; k += 32) {
        float v = xl[(size_t)w * D + k];
        s1 = fmaf(v, a_s[k], s1);
        s2 = fmaf(v, a_d[k], s2);
    }
#pragma unroll
    for (int o = 16; o; o >>= 1) {
        s1 += __shfl_xor_sync(0xffffffffu, s1, o);
        s2 += __shfl_xor_sync(0xffffffffu, s2, o);
    }
    if (lane == 0) { g_asrc[w] = s1; g_adst[w] = s2; }
}

// c = dot(We_row, a_e)  (EDIM==1 so the edge attention term is just w_e * c)
template <int D>
__global__ void k_cterm(const float* __restrict__ We, const float* __restrict__ ae) {
    float s = 0.f;
    for (int k = threadIdx.x; k < D; k += 32) s = fmaf(We[k], ae[k], s);
#pragma unroll
    for (int o = 16; o; o >>= 1) s += __shfl_xor_sync(0xffffffffu, s, o);
    if (threadIdx.x == 0) g_c[0] = s;
}

__device__ __forceinline__ float lrelu(float a) { return fmaxf(a, 0.2f * a); }

// ---------------- warp-per-node softmax aggregation ----------------
template <int D, bool HE, bool RELU>
__global__ void k_agg(const float* __restrict__ xl, const float* __restrict__ bias,
                      float* __restrict__ out, int n) {
    int i = (blockIdx.x * blockDim.x + threadIdx.x) >> 5;
    int lane = threadIdx.x & 31;
    if (i >= n) return;
    const float c = HE ? g_c[0] : 0.f;
    int rp0 = g_rowptr[i], rp1 = g_rowptr[i + 1];
    float adsti = g_adst[i];

    // self-loop logit (fill_value='mean' for edge attr)
    float aloop = g_asrc[i] + adsti + (HE ? g_meanw[i] * c : 0.f);
    aloop = lrelu(aloop);

    // sweep 1: segment max
    float m = aloop;
    for (int e = rp0 + lane; e < rp1; e += 32) {
        float a = g_asrc[g_srcs[e]] + adsti + (HE ? g_ws[e] * c : 0.f);
        m = fmaxf(m, lrelu(a));
    }
#pragma unroll
    for (int o = 16; o; o >>= 1) m = fmaxf(m, __shfl_xor_sync(0xffffffffu, m, o));

    // sweep 2: fused exp-sum + unnormalized weighted accumulate
    constexpr int F = D / 32;
    float acc[F];
    float exl = __expf(aloop - m);
#pragma unroll
    for (int f = 0; f < F; f++) acc[f] = exl * xl[(size_t)i * D + lane + 32 * f];

    float den = 0.f;
    for (int base = rp0; base < rp1; base += 32) {
        int e = base + lane;
        int s = 0;
        float ex = 0.f;
        if (e < rp1) {
            s = g_srcs[e];
            float a = lrelu(g_asrc[s] + adsti + (HE ? g_ws[e] * c : 0.f));
            ex = __expf(a - m);
            den += ex;
        }
        int cnt = min(32, rp1 - base);
        for (int j = 0; j < cnt; j++) {
            float exj = __shfl_sync(0xffffffffu, ex, j);
            int sj = __shfl_sync(0xffffffffu, s, j);
            const float* row = xl + (size_t)sj * D;
#pragma unroll
            for (int f = 0; f < F; f++) acc[f] = fmaf(exj, row[lane + 32 * f], acc[f]);
        }
    }
#pragma unroll
    for (int o = 16; o; o >>= 1) den += __shfl_xor_sync(0xffffffffu, den, o);
    den += exl;
    float inv = 1.f / den;
#pragma unroll
    for (int f = 0; f < F; f++) {
        float v = acc[f] * inv + bias[lane + 32 * f];
        if (RELU) v = fmaxf(v, 0.f);
        out[(size_t)i * D + lane + 32 * f] = v;
    }
}

// ---------------- launch ----------------
extern "C" void kernel_launch(void* const* d_in, const int* in_sizes, int n_in,
                              void* d_out, int out_size) {
    const float* x   = (const float*)d_in[0];
    const void*  ei  = d_in[1];
    const float* ew  = (const float*)d_in[2];
    const float* W0  = (const float*)d_in[3];
    const float* as0 = (const float*)d_in[4];
    const float* ad0 = (const float*)d_in[5];
    const float* ae0 = (const float*)d_in[6];
    const float* We0 = (const float*)d_in[7];
    const float* b0  = (const float*)d_in[8];
    const float* W1  = (const float*)d_in[9];
    const float* as1 = (const float*)d_in[10];
    const float* ad1 = (const float*)d_in[11];
    const float* ae1 = (const float*)d_in[12];
    const float* We1 = (const float*)d_in[13];
    const float* b1  = (const float*)d_in[14];
    const float* Wm  = (const float*)d_in[15];
    const float* asm_= (const float*)d_in[16];
    const float* adm = (const float*)d_in[17];
    const float* aem = (const float*)d_in[18];
    const float* Wem = (const float*)d_in[19];
    const float* bm  = (const float*)d_in[20];
    const float* Wl  = (const float*)d_in[21];
    const float* asl = (const float*)d_in[22];
    const float* adl = (const float*)d_in[23];
    const float* bl  = (const float*)d_in[24];
    float* out = (float*)d_out;

    int N = in_sizes[0] / 128;
    int E = in_sizes[1] / 2;
    if (N > MAXN) N = MAXN;
    if (E > MAXE) E = MAXE;
    int NB = (N + 1023) / 1024;

    void* p;
    cudaGetSymbolAddress(&p, g_xl); float* pxl = (float*)p;
    cudaGetSymbolAddress(&p, g_h);  float* ph  = (float*)p;

    // graph prep (per call; deterministic)
    k_detect<<<1, 256>>>((const unsigned int*)ei, (long long)2 * E);
    k_extract<<<(E + 255) / 256, 256>>>(ei, E);
    k_zero<<<(N + 255) / 256, 256>>>(N);
    k_count<<<(E + 255) / 256, 256>>>(ew, E);
    k_scanA<<<NB, 1024>>>(N);
    k_scanB<<<1, 32>>>(NB, N);
    k_scanC<<<NB, 1024>>>(N);
    k_fill<<<(E + 255) / 256, 256>>>(ew, E);
    k_meanw<<<(N + 255) / 256, 256>>>(N);

    int gemmBlocks = (N + 127) / 128;
    int warpBlocks = (N * 32 + 255) / 256;

    // layer 0: 128 -> 128, edge attention, ReLU
    k_gemm<128><<<gemmBlocks, 256>>>(x, W0, pxl, N);
    k_dots<128><<<warpBlocks, 256>>>(pxl, as0, ad0, N);
    k_cterm<128><<<1, 32>>>(We0, ae0);
    k_agg<128, true, true><<<warpBlocks, 256>>>(pxl, b0, ph, N);

    // layer 1: 128 -> 128, edge attention, ReLU
    k_gemm<128><<<gemmBlocks, 256>>>(ph, W1, pxl, N);
    k_dots<128><<<warpBlocks, 256>>>(pxl, as1, ad1, N);
    k_cterm<128><<<1, 32>>>(We1, ae1);
    k_agg<128, true, true><<<warpBlocks, 256>>>(pxl, b1, ph, N);

    // conv_mu: 128 -> 64, edge attention, no ReLU -> out[0 : N*64]
    k_gemm<64><<<gemmBlocks, 256>>>(ph, Wm, pxl, N);
    k_dots<64><<<warpBlocks, 256>>>(pxl, asm_, adm, N);
    k_cterm<64><<<1, 32>>>(Wem, aem);
    k_agg<64, true, false><<<warpBlocks, 256>>>(pxl, bm, out, N);

    // conv_logstd: 128 -> 64, NO edge attention, no ReLU -> out[N*64 : 2*N*64]
    k_gemm<64><<<gemmBlocks, 256>>>(ph, Wl, pxl, N);
    k_dots<64><<<warpBlocks, 256>>>(pxl, asl, adl, N);
    k_agg<64, false, false><<<warpBlocks, 256>>>(pxl, bl, out + (size_t)N * 64, N);
}

// round 2
// speedup vs baseline: 1.0548x; 1.0548x over previous
#include <cuda_runtime.h>
#include <cstdint>
#include <cstddef>

// ---------------- static device scratch (no allocations allowed) ----------------
#define MAXN 100352
#define MAXE 1601536
#define MAXNB 128

__device__ int   g_srcE[MAXE];
__device__ int   g_dstE[MAXE];
__device__ int   g_srcs[MAXE];     // src sorted by dst (CSR order)
__device__ float g_ws[MAXE];       // edge weight in CSR order
__device__ int   g_deg[MAXN];
__device__ int   g_fill[MAXN];
__device__ int   g_rowptr[MAXN + 1];
__device__ float g_sumw[MAXN];
__device__ float g_meanw[MAXN];
__device__ float g_xl[(size_t)MAXN * 128];
__device__ float g_h[(size_t)MAXN * 128];
__device__ float g_as[MAXN];
__device__ float g_ad[MAXN];
__device__ float g_as2[MAXN];
__device__ float g_ad2[MAXN];
__device__ float g_c[1];
__device__ float g_c2[1];
__device__ int   g_is64[1];
__device__ int   g_bsums[MAXNB];
__device__ int   g_boffs[MAXNB];
__device__ float g_Wcat[128 * 128];

// ---------------- init: zero arrays + detect int64 vs int32 edge_index ----------------
__global__ void k_init(const unsigned int* p, long long nwords, int n) {
    int i = blockIdx.x * blockDim.x + threadIdx.x;
    if (i < n) { g_deg[i] = 0; g_fill[i] = 0; g_sumw[i] = 0.f; }
    if (blockIdx.x == 0) {
        __shared__ int s_any;
        if (threadIdx.x == 0) s_any = 0;
        __syncthreads();
        int any = 0;
        for (int j = 0; j < 32; j++) {
            long long idx = 1 + 2LL * (threadIdx.x * 32 + j);
            if (idx < nwords && p[idx] != 0u) any = 1;
        }
        if (any) atomicOr(&s_any, 1);
        __syncthreads();
        if (threadIdx.x == 0) g_is64[0] = (s_any == 0) ? 1 : 0;
    }
}

__global__ void k_extract(const void* ei, int E) {
    int i = blockIdx.x * blockDim.x + threadIdx.x;
    if (i >= E) return;
    if (g_is64[0]) {
        const long long* p = (const long long*)ei;
        g_srcE[i] = (int)p[i];
        g_dstE[i] = (int)p[(size_t)E + i];
    } else {
        const int* p = (const int*)ei;
        g_srcE[i] = p[i];
        g_dstE[i] = p[E + i];
    }
}

__global__ void k_count(const float* __restrict__ w, int E) {
    int i = blockIdx.x * blockDim.x + threadIdx.x;
    if (i >= E) return;
    int d = g_dstE[i];
    atomicAdd(&g_deg[d], 1);
    atomicAdd(&g_sumw[d], w[i]);
}

__global__ void k_scanA(int n) {
    __shared__ int s[1024];
    int b = blockIdx.x, t = threadIdx.x;
    int i = b * 1024 + t;
    int v = (i < n) ? g_deg[i] : 0;
    s[t] = v;
    __syncthreads();
    for (int off = 1; off < 1024; off <<= 1) {
        int x = (t >= off) ? s[t - off] : 0;
        __syncthreads();
        s[t] += x;
        __syncthreads();
    }
    if (i < n) g_rowptr[i] = s[t] - v;
    if (t == 1023) g_bsums[b] = s[1023];
}

__global__ void k_scanB(int nb, int n) {
    if (threadIdx.x == 0) {
        int run = 0;
        for (int b = 0; b < nb; b++) { g_boffs[b] = run; run += g_bsums[b]; }
        g_rowptr[n] = run;
    }
}

// final rowptr + mean edge weight per node
__global__ void k_scanC(int n) {
    int i = blockIdx.x * 1024 + threadIdx.x;
    if (i < n) {
        g_rowptr[i] += g_boffs[blockIdx.x];
        int d = g_deg[i];
        g_meanw[i] = (d > 0) ? g_sumw[i] / (float)d : 0.f;
    }
}

__global__ void k_fill(const float* __restrict__ w, int E) {
    int i = blockIdx.x * blockDim.x + threadIdx.x;
    if (i >= E) return;
    int d = g_dstE[i];
    int pos = g_rowptr[d] + atomicAdd(&g_fill[d], 1);
    g_srcs[pos] = g_srcE[i];
    g_ws[pos] = w[i];
}

__global__ void k_wcat(const float* __restrict__ Wm, const float* __restrict__ Wl) {
    int i = blockIdx.x * blockDim.x + threadIdx.x;   // i over 128*128
    int k = i >> 7, j = i & 127;
    g_Wcat[i] = (j < 64) ? Wm[k * 64 + j] : Wl[k * 64 + (j - 64)];
}

// ---------------- GEMM: C[n,128] = A[n,128] @ W[128,128] ----------------
// 128 threads, 8x16 register tile, conflict-free float4 LDS.
__global__ __launch_bounds__(128) void k_gemm128(const float* __restrict__ A,
                                                 const float* __restrict__ W,
                                                 float* __restrict__ C, int n) {
    __shared__ __align__(16) float Xs[32 * 132];   // transposed: Xs[k][row], stride 132
    __shared__ __align__(16) float Wsm[32 * 128];  // Wsm[k][col]
    int t = threadIdx.x;
    int tx = t & 7, ty = t >> 3;                   // tx 0..7 (cols), ty 0..15 (rows)
    int row0 = blockIdx.x * 128;

    float acc[8][16];
#pragma unroll
    for (int i = 0; i < 8; i++)
#pragma unroll
        for (int j = 0; j < 16; j++) acc[i][j] = 0.f;

    for (int k0 = 0; k0 < 128; k0 += 32) {
        // X tile (transposed store). Per warp: 4 full 128B rows per iteration.
#pragma unroll
        for (int it = 0; it < 8; ++it) {
            int row = (t >> 3) + 16 * it;
            int k4 = (t & 7) * 4;
            float4 v = make_float4(0.f, 0.f, 0.f, 0.f);
            int gr = row0 + row;
            if (gr < n) v = *(const float4*)&A[(size_t)gr * 128 + k0 + k4];
            Xs[(k4 + 0) * 132 + row] = v.x;
            Xs[(k4 + 1) * 132 + row] = v.y;
            Xs[(k4 + 2) * 132 + row] = v.z;
            Xs[(k4 + 3) * 132 + row] = v.w;
        }
        // W tile
#pragma unroll
        for (int it = 0; it < 8; ++it) {
            int idx = t + 128 * it;                // float4 index over 1024
            int kk = idx >> 5;
            int c4 = (idx & 31) * 4;
            *(float4*)&Wsm[kk * 128 + c4] = *(const float4*)&W[(size_t)(k0 + kk) * 128 + c4];
        }
        __syncthreads();
#pragma unroll
        for (int k = 0; k < 32; k++) {
            float4 a0 = *(const float4*)&Xs[k * 132 + ty * 8];
            float4 a1 = *(const float4*)&Xs[k * 132 + ty * 8 + 4];
            float av[8] = {a0.x, a0.y, a0.z, a0.w, a1.x, a1.y, a1.z, a1.w};
            float bv[16];
#pragma unroll
            for (int jj = 0; jj < 4; jj++) {
                float4 b4 = *(const float4*)&Wsm[k * 128 + tx * 4 + 32 * jj];
                bv[jj * 4 + 0] = b4.x; bv[jj * 4 + 1] = b4.y;
                bv[jj * 4 + 2] = b4.z; bv[jj * 4 + 3] = b4.w;
            }
#pragma unroll
            for (int i = 0; i < 8; i++)
#pragma unroll
                for (int j = 0; j < 16; j++) acc[i][j] = fmaf(av[i], bv[j], acc[i][j]);
        }
        __syncthreads();
    }
#pragma unroll
    for (int i = 0; i < 8; i++) {
        int r = row0 + ty * 8 + i;
        if (r < n) {
#pragma unroll
            for (int jj = 0; jj < 4; jj++) {
                float4 v = make_float4(acc[i][jj * 4 + 0], acc[i][jj * 4 + 1],
                                       acc[i][jj * 4 + 2], acc[i][jj * 4 + 3]);
                *(float4*)&C[(size_t)r * 128 + tx * 4 + 32 * jj] = v;
            }
        }
    }
}

// ---------------- attention logit dots (wide layers, D=128), + cterm fold ----------------
__global__ void k_dots128(const float* __restrict__ xl, const float* __restrict__ a_s,
                          const float* __restrict__ a_d,
                          const float* __restrict__ We, const float* __restrict__ ae,
                          float* __restrict__ asrc, float* __restrict__ adst,
                          float* __restrict__ cout, int n) {
    int warpid = threadIdx.x >> 5;
    int lane = threadIdx.x & 31;
    if (warpid == 8) {                         // extra warp: cterm (block 0 only)
        if (blockIdx.x == 0 && cout) {
            float s = 0.f;
            for (int k = lane; k < 128; k += 32) s = fmaf(We[k], ae[k], s);
#pragma unroll
            for (int o = 16; o; o >>= 1) s += __shfl_xor_sync(0xffffffffu, s, o);
            if (lane == 0) cout[0] = s;
        }
        return;
    }
    int w = blockIdx.x * 8 + warpid;
    if (w >= n) return;
    const float4* row = (const float4*)(xl + (size_t)w * 128);
    float4 v = row[lane];
    float s1 = v.x * a_s[lane * 4] + v.y * a_s[lane * 4 + 1] + v.z * a_s[lane * 4 + 2] + v.w * a_s[lane * 4 + 3];
    float s2 = v.x * a_d[lane * 4] + v.y * a_d[lane * 4 + 1] + v.z * a_d[lane * 4 + 2] + v.w * a_d[lane * 4 + 3];
#pragma unroll
    for (int o = 16; o; o >>= 1) {
        s1 += __shfl_xor_sync(0xffffffffu, s1, o);
        s2 += __shfl_xor_sync(0xffffffffu, s2, o);
    }
    if (lane == 0) { asrc[w] = s1; adst[w] = s2; }
}

// combined dots for concatenated mu|logstd xl [N,128]; one row read, four dots. + mu cterm
__global__ void k_dots2(const float* __restrict__ xl,
                        const float* __restrict__ asM, const float* __restrict__ adM,
                        const float* __restrict__ asL, const float* __restrict__ adL,
                        const float* __restrict__ Wem, const float* __restrict__ aem,
                        int n) {
    int warpid = threadIdx.x >> 5;
    int lane = threadIdx.x & 31;
    if (warpid == 8) {
        if (blockIdx.x == 0) {
            float s = 0.f;
            for (int k = lane; k < 64; k += 32) s = fmaf(Wem[k], aem[k], s);
#pragma unroll
            for (int o = 16; o; o >>= 1) s += __shfl_xor_sync(0xffffffffu, s, o);
            if (lane == 0) g_c[0] = s;
        }
        return;
    }
    int w = blockIdx.x * 8 + warpid;
    if (w >= n) return;
    const float4* row = (const float4*)(xl + (size_t)w * 128);
    float4 v = row[lane];
    // lanes 0..15 -> mu cols 0..63 ; lanes 16..31 -> logstd cols 0..63
    int base = (lane & 15) * 4;
    const float* avs = (lane < 16) ? asM : asL;
    const float* avd = (lane < 16) ? adM : adL;
    float s1 = v.x * avs[base] + v.y * avs[base + 1] + v.z * avs[base + 2] + v.w * avs[base + 3];
    float s2 = v.x * avd[base] + v.y * avd[base + 1] + v.z * avd[base + 2] + v.w * avd[base + 3];
#pragma unroll
    for (int o = 8; o; o >>= 1) {
        s1 += __shfl_xor_sync(0xffffffffu, s1, o);
        s2 += __shfl_xor_sync(0xffffffffu, s2, o);
    }
    if (lane == 0)  { g_as[w]  = s1; g_ad[w]  = s2; }
    if (lane == 16) { g_as2[w] = s1; g_ad2[w] = s2; }
}

__device__ __forceinline__ float lrelu(float a) { return fmaxf(a, 0.2f * a); }

// ---------------- warp-per-node softmax aggregation (vectorized gather) ----------------
// xl row = xl + s*LD + OFF; out row = out + i*D (contiguous)
template <int D, bool HE, bool RELU>
__global__ void k_agg(const float* __restrict__ xl, int LD, int OFF,
                      const float* __restrict__ asrc, const float* __restrict__ adst,
                      const float* __restrict__ cp,
                      const float* __restrict__ bias, float* __restrict__ out, int n) {
    int i = (blockIdx.x * blockDim.x + threadIdx.x) >> 5;
    int lane = threadIdx.x & 31;
    if (i >= n) return;
    const float c = HE ? cp[0] : 0.f;
    int rp0 = g_rowptr[i], rp1 = g_rowptr[i + 1];
    float adsti = adst[i];

    float aloop = asrc[i] + adsti + (HE ? g_meanw[i] * c : 0.f);
    aloop = lrelu(aloop);

    // sweep 1: segment max
    float m = aloop;
    for (int e = rp0 + lane; e < rp1; e += 32) {
        float a = asrc[g_srcs[e]] + adsti + (HE ? g_ws[e] * c : 0.f);
        m = fmaxf(m, lrelu(a));
    }
#pragma unroll
    for (int o = 16; o; o >>= 1) m = fmaxf(m, __shfl_xor_sync(0xffffffffu, m, o));

    constexpr int V = D / 32;                       // 4 (D=128) or 2 (D=64)
    float acc[V];
    float exl = __expf(aloop - m);
    {
        const float* rowi = xl + (size_t)i * LD + OFF;
        if (V == 4) {
            float4 v = *(const float4*)&rowi[lane * 4];
            acc[0] = exl * v.x; acc[1] = exl * v.y;
            if (V > 2) { acc[V - 2] = exl * v.z; acc[V - 1] = exl * v.w; }
        } else {
            float2 v = *(const float2*)&rowi[lane * 2];
            acc[0] = exl * v.x; acc[1] = exl * v.y;
        }
    }

    float den = 0.f;
    for (int base = rp0; base < rp1; base += 32) {
        int e = base + lane;
        int s = 0;
        float ex = 0.f;
        if (e < rp1) {
            s = g_srcs[e];
            float a = lrelu(asrc[s] + adsti + (HE ? g_ws[e] * c : 0.f));
            ex = __expf(a - m);
            den += ex;
        }
        int cnt = min(32, rp1 - base);
        for (int j = 0; j < cnt; j++) {
            float exj = __shfl_sync(0xffffffffu, ex, j);
            int sj = __shfl_sync(0xffffffffu, s, j);
            const float* row = xl + (size_t)sj * LD + OFF;
            if (V == 4) {
                float4 v = *(const float4*)&row[lane * 4];
                acc[0] = fmaf(exj, v.x, acc[0]);
                acc[1] = fmaf(exj, v.y, acc[1]);
                acc[V - 2] = fmaf(exj, v.z, acc[V - 2]);
                acc[V - 1] = fmaf(exj, v.w, acc[V - 1]);
            } else {
                float2 v = *(const float2*)&row[lane * 2];
                acc[0] = fmaf(exj, v.x, acc[0]);
                acc[1] = fmaf(exj, v.y, acc[1]);
            }
        }
    }
#pragma unroll
    for (int o = 16; o; o >>= 1) den += __shfl_xor_sync(0xffffffffu, den, o);
    den += exl;
    float inv = 1.f / den;
#pragma unroll
    for (int f = 0; f < V; f++) {
        float v = acc[f] * inv + bias[lane * V + f];
        if (RELU) v = fmaxf(v, 0.f);
        out[(size_t)i * D + lane * V + f] = v;
    }
}

// ---------------- launch ----------------
extern "C" void kernel_launch(void* const* d_in, const int* in_sizes, int n_in,
                              void* d_out, int out_size) {
    const float* x   = (const float*)d_in[0];
    const void*  ei  = d_in[1];
    const float* ew  = (const float*)d_in[2];
    const float* W0  = (const float*)d_in[3];
    const float* as0 = (const float*)d_in[4];
    const float* ad0 = (const float*)d_in[5];
    const float* ae0 = (const float*)d_in[6];
    const float* We0 = (const float*)d_in[7];
    const float* b0  = (const float*)d_in[8];
    const float* W1  = (const float*)d_in[9];
    const float* as1 = (const float*)d_in[10];
    const float* ad1 = (const float*)d_in[11];
    const float* ae1 = (const float*)d_in[12];
    const float* We1 = (const float*)d_in[13];
    const float* b1  = (const float*)d_in[14];
    const float* Wm  = (const float*)d_in[15];
    const float* asm_= (const float*)d_in[16];
    const float* adm = (const float*)d_in[17];
    const float* aem = (const float*)d_in[18];
    const float* Wem = (const float*)d_in[19];
    const float* bm  = (const float*)d_in[20];
    const float* Wl  = (const float*)d_in[21];
    const float* asl = (const float*)d_in[22];
    const float* adl = (const float*)d_in[23];
    const float* bl  = (const float*)d_in[24];
    float* out = (float*)d_out;

    int N = in_sizes[0] / 128;
    int E = in_sizes[1] / 2;
    if (N > MAXN) N = MAXN;
    if (E > MAXE) E = MAXE;
    int NB = (N + 1023) / 1024;

    void* p;
    cudaGetSymbolAddress(&p, g_xl);   float* pxl  = (float*)p;
    cudaGetSymbolAddress(&p, g_h);    float* ph   = (float*)p;
    cudaGetSymbolAddress(&p, g_Wcat); float* pWc  = (float*)p;
    cudaGetSymbolAddress(&p, g_as);   float* pas  = (float*)p;
    cudaGetSymbolAddress(&p, g_ad);   float* pad_ = (float*)p;
    cudaGetSymbolAddress(&p, g_as2);  float* pas2 = (float*)p;
    cudaGetSymbolAddress(&p, g_ad2);  float* pad2 = (float*)p;
    cudaGetSymbolAddress(&p, g_c);    float* pc   = (float*)p;

    // graph prep
    k_init<<<(N + 255) / 256, 256>>>((const unsigned int*)ei, (long long)2 * E, N);
    k_extract<<<(E + 255) / 256, 256>>>(ei, E);
    k_count<<<(E + 255) / 256, 256>>>(ew, E);
    k_scanA<<<NB, 1024>>>(N);
    k_scanB<<<1, 32>>>(NB, N);
    k_scanC<<<NB, 1024>>>(N);
    k_fill<<<(E + 255) / 256, 256>>>(ew, E);
    k_wcat<<<64, 256>>>(Wm, Wl);

    int gemmBlocks = (N + 127) / 128;
    int dotBlocks  = (N + 7) / 8;
    int aggBlocks  = (N * 32 + 255) / 256;

    // layer 0
    k_gemm128<<<gemmBlocks, 128>>>(x, W0, pxl, N);
    k_dots128<<<dotBlocks, 288>>>(pxl, as0, ad0, We0, ae0, pas, pad_, pc, N);
    k_agg<128, true, true><<<aggBlocks, 256>>>(pxl, 128, 0, pas, pad_, pc, b0, ph, N);

    // layer 1
    k_gemm128<<<gemmBlocks, 128>>>(ph, W1, pxl, N);
    k_dots128<<<dotBlocks, 288>>>(pxl, as1, ad1, We1, ae1, pas, pad_, pc, N);
    k_agg<128, true, true><<<aggBlocks, 256>>>(pxl, 128, 0, pas, pad_, pc, b1, ph, N);

    // mu + logstd combined GEMM (cols 0..63 = mu, 64..127 = logstd)
    k_gemm128<<<gemmBlocks, 128>>>(ph, pWc, pxl, N);
    k_dots2<<<dotBlocks, 288>>>(pxl, asm_, adm, asl, adl, Wem, aem, N);
    k_agg<64, true,  false><<<aggBlocks, 256>>>(pxl, 128, 0,  pas,  pad_, pc, bm, out, N);
    k_agg<64, false, false><<<aggBlocks, 256>>>(pxl, 128, 64, pas2, pad2, pc, bl, out + (size_t)N * 64, N);
}